// round 11
// baseline (speedup 1.0000x reference)
#include <cuda_runtime.h>
#include <cuda_bf16.h>
#include <cuda_fp16.h>
#include <stdint.h>

#define HDIM   256
#define BATCH  32
#define TSTEPS 4096
#define EDGES  8192
#define D2     512
#define MTOT   (TSTEPS * BATCH)   // 131072

// ---------------- scratch (static device globals; no runtime alloc) ----------------
__device__ __align__(16) __half  g_ph[BATCH * D2];   // fp16(W1*hidden + b_attn) [b][d]
__device__ __align__(16) __half  g_W2h[D2 * HDIM];   // fp16(W_attn[:,256:512]) [n][k]
__device__ __align__(16) float   g_e[MTOT];          // exp(score)  [b*4096 + t]  (b-major)
__device__ __align__(16) float   g_sum[BATCH];       // per-batch softmax denom

__device__ __forceinline__ uint32_t smem_u32(const void* p) {
    uint32_t a;
    asm("{ .reg .u64 t; cvta.to.shared.u64 t, %1; cvt.u32.u64 %0, t; }" : "=r"(a) : "l"(p));
    return a;
}
__device__ __forceinline__ float tanh_fast(float x) {
    float t;
    asm("tanh.approx.f32 %0, %1;" : "=f"(t) : "f"(x));
    return t;
}
__device__ __forceinline__ void cp_async16(uint32_t dst, const void* src) {
    asm volatile("cp.async.ca.shared.global [%0], [%1], 16;" :: "r"(dst), "l"(src));
}
#define CP_COMMIT() asm volatile("cp.async.commit_group;" ::: "memory")
#define CP_WAIT0()  asm volatile("cp.async.wait_group 0;" ::: "memory")

// ---------------- kernel 1: p = fp16(W1*hidden + b_attn) ; W2 -> fp16 (x4 vec) ----------------
__global__ void prep_kernel(const float* __restrict__ hidden,
                            const float* __restrict__ W,
                            const float* __restrict__ ba) {
    int tid = threadIdx.x, lid = tid & 31;
    int gw = blockIdx.x * 8 + (tid >> 5);        // 2048 blocks x 8 warps = 16384 outputs
    int b = gw >> 9, d = gw & 511;
    const float* wr = W + (size_t)d * 512;       // W1 = W_attn[:, 0:256]
    const float* hr = hidden + b * HDIM;
    float s = 0.f;
    #pragma unroll
    for (int k = lid; k < HDIM; k += 32) s += wr[k] * hr[k];
    #pragma unroll
    for (int o = 16; o > 0; o >>= 1) s += __shfl_xor_sync(0xFFFFFFFF, s, o);
    if (lid == 0) g_ph[gw] = __float2half_rn(s + ba[d]);   // gw == b*512 + d

    int gt = blockIdx.x * 256 + tid;             // 524288 threads, first 32768 convert W2 x4
    if (gt < D2 * HDIM / 4) {
        int n = gt >> 6, k4 = gt & 63;           // 64 float4 per 256-col row
        float4 w = *reinterpret_cast<const float4*>(W + (size_t)n * 512 + HDIM + k4 * 4);
        __half2 lo = __floats2half2_rn(w.x, w.y);
        __half2 hi = __floats2half2_rn(w.z, w.w);
        uint2 val;
        val.x = *reinterpret_cast<uint32_t*>(&lo);
        val.y = *reinterpret_cast<uint32_t*>(&hi);
        *reinterpret_cast<uint2*>(g_W2h + (size_t)n * 256 + k4 * 4) = val;
    }
    if (gt < BATCH) g_sum[gt] = 0.f;
}

// ---------------- kernel 2: mma.sync fp16-in fp32-acc GEMM, latency-hidden loads ----------------
// CTA: 128 M-rows, 8 warps (warp tile 16x64), 8 N-chunks of 64, occupancy 2.
// B single-buffered (next chunk issued post-kk-loop, covered by epilogue);
// p double-buffered fp16 (stride 144 B = 72 halves, conflict-free, cp.async aligned).
static constexpr int SM_A     = 0;        // 128 rows x 512 B (fp16 k=256, swizzled) = 65536
static constexpr int SM_B     = 65536;    // 64 rows x 512 B                         = 32768
static constexpr int SM_P0    = 98304;    // 32 x 144 B                              = 4608
static constexpr int SM_P1    = 102912;   //                                         = 4608
static constexpr int SM_V     = 107520;   // 512 floats                              = 2048
static constexpr int SM_BS    = 109568;   // 32 floats                               = 128
static constexpr int SM_TOTAL = 109696;

__device__ __forceinline__ void load_B_chunk(uint32_t sb, int c, int tid) {
    const char* bsrc = (const char*)(g_W2h + (size_t)c * 64 * HDIM);   // 32 KB
    #pragma unroll
    for (int i = tid; i < 2048; i += 256) {
        int row = i >> 5, k16 = i & 31;
        cp_async16(sb + SM_B + row * 512 + ((k16 ^ (row & 7)) << 4), bsrc + i * 16);
    }
}
__device__ __forceinline__ void load_p_chunk(uint32_t sb, int c, int buf, int tid) {
    // 32 b-rows x 64 halves = 128 B/row -> 8 x 16B per row; 256 threads cover exactly
    int pb = tid >> 3, j16 = tid & 7;
    cp_async16(sb + (buf ? SM_P1 : SM_P0) + pb * 144 + j16 * 16,
               (const char*)(g_ph + pb * 512 + c * 64 + j16 * 8));
}

__global__ __launch_bounds__(256, 2)
void attn_gemm_kernel(const float* __restrict__ enc, const float* __restrict__ v,
                      float* __restrict__ out) {
    extern __shared__ char smem[];
    uint32_t sb = smem_u32(smem);
    int tid = threadIdx.x, wid = tid >> 5, lid = tid & 31;
    int gid = lid >> 2, tg = lid & 3;

    float* v_s  = (float*)(smem + SM_V);
    float* bsum = (float*)(smem + SM_BS);
    if (tid < 32) bsum[tid] = 0.f;

    // ---- prologue: async-load B chunk 0 + p chunk 0 + v (covered by A preamble) ----
    load_B_chunk(sb, 0, tid);
    load_p_chunk(sb, 0, 0, tid);
    if (tid < 128) cp_async16(sb + SM_V + tid * 16, (const char*)(v + tid * 4));
    CP_COMMIT();

    // ---- zero this CTA's 512B slice of out (coalesced, hidden under cp.async) ----
    if (tid < 128) out[blockIdx.x * 128 + tid] = 0.f;

    // ---- A: enc rows [blk*128, +128): fp32 -> fp16, swizzled smem ----
    const float4* asrc = (const float4*)(enc + (size_t)blockIdx.x * 128 * HDIM);
    for (int i = tid; i < 4096; i += 256) {
        int row = i >> 5, k16 = i & 31;
        float4 a = asrc[row * 64 + k16 * 2];
        float4 b = asrc[row * 64 + k16 * 2 + 1];
        __half2 t0 = __floats2half2_rn(a.x, a.y);
        __half2 t1 = __floats2half2_rn(a.z, a.w);
        __half2 t2 = __floats2half2_rn(b.x, b.y);
        __half2 t3 = __floats2half2_rn(b.z, b.w);
        uint4 val;
        val.x = *reinterpret_cast<uint32_t*>(&t0);
        val.y = *reinterpret_cast<uint32_t*>(&t1);
        val.z = *reinterpret_cast<uint32_t*>(&t2);
        val.w = *reinterpret_cast<uint32_t*>(&t3);
        *reinterpret_cast<uint4*>(smem + SM_A + row * 512 + ((k16 ^ (row & 7)) << 4)) = val;
    }

    // ---- per-lane ldmatrix addressing (layout validated R2..R10) ----
    int arow = wid * 16 + (lid & 7) + (lid & 8);
    uint32_t aoff = sb + SM_A + arow * 512;
    uint32_t asw  = (uint32_t)(arow & 7);
    uint32_t ahalf = (lid >> 4) & 1;
    int bn = (lid & 7) + (((lid >> 4) & 1) << 3);
    uint32_t boff = sb + SM_B + bn * 512;
    uint32_t bsw  = (uint32_t)(bn & 7);
    uint32_t bhalf = (lid >> 3) & 1;

    float rs[2] = {0.f, 0.f};   // partial scores for rows (gid), (gid+8)

    for (int c = 0; c < 8; c++) {
        CP_WAIT0();
        __syncthreads();        // chunk c B/p (and, at c==0, A/v) visible to all warps

        float acc[8][4];
        #pragma unroll
        for (int j = 0; j < 8; j++)
            #pragma unroll
            for (int r = 0; r < 4; r++) acc[j][r] = 0.f;

        #pragma unroll
        for (int kk = 0; kk < 16; kk++) {
            uint32_t ak = (((2u * kk + ahalf) ^ asw) << 4);
            uint32_t bk = (((2u * kk + bhalf) ^ bsw) << 4);
            uint32_t a[4], br[16];
            asm volatile("ldmatrix.sync.aligned.m8n8.x4.shared.b16 {%0,%1,%2,%3}, [%4];"
                : "=r"(a[0]), "=r"(a[1]), "=r"(a[2]), "=r"(a[3]) : "r"(aoff + ak));
            #pragma unroll
            for (int t = 0; t < 4; t++) {
                asm volatile("ldmatrix.sync.aligned.m8n8.x4.shared.b16 {%0,%1,%2,%3}, [%4];"
                    : "=r"(br[4 * t]), "=r"(br[4 * t + 1]),
                      "=r"(br[4 * t + 2]), "=r"(br[4 * t + 3])
                    : "r"(boff + (uint32_t)t * 8192 + bk));
            }
            #pragma unroll
            for (int j = 0; j < 8; j++) {
                asm volatile(
                    "mma.sync.aligned.m16n8k16.row.col.f32.f16.f16.f32 "
                    "{%0,%1,%2,%3}, {%4,%5,%6,%7}, {%8,%9}, {%0,%1,%2,%3};"
                    : "+f"(acc[j][0]), "+f"(acc[j][1]), "+f"(acc[j][2]), "+f"(acc[j][3])
                    : "r"(a[0]), "r"(a[1]), "r"(a[2]), "r"(a[3]),
                      "r"(br[2 * j]), "r"(br[2 * j + 1]));
            }
        }

        __syncthreads();        // all warps done reading SM_B / p-buffer for chunk c
        if (c < 7) {            // issue next chunk NOW; epilogue hides the latency
            load_B_chunk(sb, c + 1, tid);
            load_p_chunk(sb, c + 1, (c + 1) & 1, tid);
            CP_COMMIT();
        }

        // ---- fused epilogue: += v[col] * tanh(acc + p[b][col]) ----
        const float* vc = v_s + c * 64;
        const __half* psh = (const __half*)(smem + ((c & 1) ? SM_P1 : SM_P0));
        #pragma unroll
        for (int r = 0; r < 4; r++) {
            int rh = r >> 1;
            int bix = (wid * 16 + gid + (rh << 3)) & 31;
            const __half* pr = psh + bix * 72;
            float s = 0.f;
            #pragma unroll
            for (int j = 0; j < 8; j++) {
                int lcol = j * 8 + tg * 2 + (r & 1);
                s += vc[lcol] * tanh_fast(acc[j][r] + __half2float(pr[lcol]));
            }
            rs[rh] += s;
        }
    }

    // quad reduction (lanes share gid, differ in tg)
    #pragma unroll
    for (int h = 0; h < 2; h++) {
        float x = rs[h];
        x += __shfl_xor_sync(0xFFFFFFFF, x, 1);
        x += __shfl_xor_sync(0xFFFFFFFF, x, 2);
        rs[h] = x;
    }
    if (tg == 0) {
        int m0 = blockIdx.x * 128 + wid * 16 + gid;     // flattened t*32 + b
        int m1 = m0 + 8;
        float e0 = __expf(rs[0]);
        float e1 = __expf(rs[1]);
        g_e[(m0 & 31) * TSTEPS + (m0 >> 5)] = e0;       // b-major layout
        g_e[(m1 & 31) * TSTEPS + (m1 >> 5)] = e1;
        atomicAdd(&bsum[m0 & 31], e0);
        atomicAdd(&bsum[m1 & 31], e1);
    }
    __syncthreads();
    if (tid < 32) atomicAdd(&g_sum[tid], bsum[tid]);
}

// ---------------- kernel 3: masked edge scatter-add, 2 edges/thread, x0.1/sum folded ----------------
__global__ void scatter_kernel(const int2* __restrict__ esrc2,
                               const int2* __restrict__ edst2,
                               float* __restrict__ out) {
    int i = blockIdx.x * 256 + threadIdx.x;     // 512 blocks x 256 = 131072 (x2 edges)
    int b = i >> 12;                            // 4096 int2-threads per batch
    int2 s2 = esrc2[i];
    int2 d2 = edst2[i];
    const float* eb = g_e + b * TSTEPS;
    float* ob = out + b * TSTEPS;
    float inv = 0.1f * __frcp_rn(g_sum[b]);
    float w0 = eb[s2.x] * inv;
    float w1 = eb[s2.y] * inv;
    if (d2.x != s2.x + 1) atomicAdd(ob + d2.x, w0);
    if (d2.y != s2.y + 1) atomicAdd(ob + d2.y, w1);
}

// ---------------- host launch ----------------
extern "C" void kernel_launch(void* const* d_in, const int* in_sizes, int n_in,
                              void* d_out, int out_size) {
    const float* hidden = (const float*)d_in[0];
    const float* enc    = (const float*)d_in[1];
    const int*   esrc   = (const int*)d_in[2];
    const int*   edst   = (const int*)d_in[3];
    const float* W      = (const float*)d_in[4];
    const float* ba     = (const float*)d_in[5];
    const float* v      = (const float*)d_in[6];
    float* out = (float*)d_out;

    cudaFuncSetAttribute(attn_gemm_kernel,
                         cudaFuncAttributeMaxDynamicSharedMemorySize, SM_TOTAL);

    prep_kernel<<<2048, 256>>>(hidden, W, ba);
    attn_gemm_kernel<<<MTOT / 128, 256, SM_TOTAL>>>(enc, v, out);
    scatter_kernel<<<BATCH * EDGES / 512, 256>>>((const int2*)esrc, (const int2*)edst, out);
}